// round 2
// baseline (speedup 1.0000x reference)
#include <cuda_runtime.h>
#include <cuda_bf16.h>
#include <cstdint>

// ---------------- problem constants ----------------
#define BATCH  1024
#define INSZ   512
#define UNITS  512
#define K12    12
#define KDIM   (INSZ * K12)      // 6144
#define KSPLIT 4
#define KPER   (KDIM / KSPLIT)   // 1536
#define TK     64                // K columns per stage (128 B/row bf16)
#define STAGES (KPER / TK)       // 24
#define PIPE   3                 // cp.async pipeline depth

// ---------------- scratch (static device globals; no allocation) ----------------
__device__ __align__(16) __nv_bfloat16 g_A[(size_t)BATCH * KDIM];     // 12.6 MB
__device__ __align__(16) __nv_bfloat16 g_Bt[(size_t)UNITS * KDIM];    // 6.3 MB
__device__ __align__(16) float         g_part[(size_t)KSPLIT * BATCH * UNITS]; // 8.4 MB

// ---------------- helpers ----------------
__device__ __forceinline__ uint32_t smem_u32(const void* p) {
    uint32_t a;
    asm("{ .reg .u64 t; cvta.to.shared.u64 t, %1; cvt.u32.u64 %0, t; }" : "=r"(a) : "l"(p));
    return a;
}
__device__ __forceinline__ uint32_t swz(uint32_t off) { return off ^ ((off >> 3) & 0x70); }

__device__ __forceinline__ void cp_async16(uint32_t saddr, const void* g) {
    asm volatile("cp.async.cg.shared.global [%0], [%1], 16;" :: "r"(saddr), "l"(g) : "memory");
}
#define CP_COMMIT() asm volatile("cp.async.commit_group;" ::: "memory")
#define CP_WAIT(N)  asm volatile("cp.async.wait_group %0;" :: "n"(N) : "memory")

__device__ __forceinline__ void ldsm_x4(uint32_t& r0, uint32_t& r1, uint32_t& r2, uint32_t& r3,
                                        uint32_t addr) {
    asm volatile("ldmatrix.sync.aligned.m8n8.x4.shared.b16 {%0,%1,%2,%3}, [%4];"
                 : "=r"(r0), "=r"(r1), "=r"(r2), "=r"(r3) : "r"(addr));
}
__device__ __forceinline__ void mma16816(float* c, const uint32_t* a, uint32_t b0, uint32_t b1) {
    asm volatile("mma.sync.aligned.m16n8k16.row.col.f32.bf16.bf16.f32 "
                 "{%0,%1,%2,%3}, {%4,%5,%6,%7}, {%8,%9}, {%0,%1,%2,%3};"
                 : "+f"(c[0]), "+f"(c[1]), "+f"(c[2]), "+f"(c[3])
                 : "r"(a[0]), "r"(a[1]), "r"(a[2]), "r"(a[3]), "r"(b0), "r"(b1));
}
__device__ __forceinline__ unsigned pkb(__nv_bfloat16 a, __nv_bfloat16 b) {
    return (unsigned)__bfloat16_as_ushort(a) | ((unsigned)__bfloat16_as_ushort(b) << 16);
}

// ---------------- kernel 1: A[b, i*12 + c] = {8 cubic B-spline bases, shi, shi, slo, 0} ----------------
__global__ void build_A(const float* __restrict__ X) {
    int lin = blockIdx.x * blockDim.x + threadIdx.x;
    if (lin >= BATCH * INSZ) return;
    float x = X[lin];

    // uniform knots t_j = -2.2 + 0.4*j, j = 0..11  (GRID=5, ORDER=3, range [-1,1])
    float bb[11];
#pragma unroll
    for (int j = 0; j < 11; j++) {
        float tj = -2.2f + 0.4f * j;
        bb[j] = (x >= tj && x < tj + 0.4f) ? 1.f : 0.f;
    }
#pragma unroll
    for (int k = 1; k <= 3; k++) {
        float inv = 1.f / (0.4f * k);
#pragma unroll
        for (int j = 0; j < 11 - k; j++) {
            float tj = -2.2f + 0.4f * j;
            float tjk1 = -2.2f + 0.4f * (j + k + 1);
            bb[j] = (x - tj) * inv * bb[j] + (tjk1 - x) * inv * bb[j + 1];
        }
    }
    float s = x / (1.f + expf(-x));  // silu
    __nv_bfloat16 shi = __float2bfloat16(s);
    __nv_bfloat16 slo = __float2bfloat16(s - __bfloat162float(shi));

    __nv_bfloat16 h[8];
#pragma unroll
    for (int j = 0; j < 8; j++) h[j] = __float2bfloat16(bb[j]);

    uint2* dst = (uint2*)(g_A + (size_t)lin * K12);
    dst[0] = make_uint2(pkb(h[0], h[1]), pkb(h[2], h[3]));
    dst[1] = make_uint2(pkb(h[4], h[5]), pkb(h[6], h[7]));
    dst[2] = make_uint2(pkb(shi, shi), pkb(slo, __float2bfloat16(0.f)));
}

// ---------------- kernel 2: Bt[o, i*12 + c] = {scale*W_k (k=0..7), schi, sclo, schi, 0} ----------------
__global__ void build_Bt(const float* __restrict__ Wk, const float* __restrict__ scale) {
    int lin = blockIdx.x * blockDim.x + threadIdx.x;
    if (lin >= UNITS * INSZ) return;
    int o = lin & (UNITS - 1);
    int i = lin >> 9;
    float sc = scale[(size_t)i * UNITS + o];

    __nv_bfloat16 c[8];
#pragma unroll
    for (int k = 0; k < 8; k++)
        c[k] = __float2bfloat16(sc * Wk[((size_t)i * 8 + k) * UNITS + o]);
    __nv_bfloat16 schi = __float2bfloat16(sc);
    __nv_bfloat16 sclo = __float2bfloat16(sc - __bfloat162float(schi));

    uint2* dst = (uint2*)(g_Bt + (size_t)o * KDIM + i * K12);
    dst[0] = make_uint2(pkb(c[0], c[1]), pkb(c[2], c[3]));
    dst[1] = make_uint2(pkb(c[4], c[5]), pkb(c[6], c[7]));
    dst[2] = make_uint2(pkb(schi, sclo), pkb(schi, __float2bfloat16(0.f)));
}

// ---------------- kernel 3: split-K bf16 mma.sync GEMM ----------------
// partial[z][m][n] = sum_{k in z-chunk} A[m,k] * Bt[n,k]
// CTA tile 128x128, K-stage 64, 3-stage cp.async pipeline, 8 warps (warp tile 32x64).
__global__ __launch_bounds__(256, 1)
void kan_gemm() {
    extern __shared__ char dyn[];
    const uint32_t base = smem_u32(dyn);   // PIPE stages of [A 16KB | B 16KB]

    const int t   = threadIdx.x;
    const int wid = t >> 5, lane = t & 31;
    const int wm  = wid & 3;               // 4 warp-rows  -> 32 m each
    const int wn  = wid >> 2;              // 2 warp-cols  -> 64 n each
    const int m0  = blockIdx.y * 128;
    const int n0  = blockIdx.x * 128;
    const int kbase = blockIdx.z * KPER;

    // ---- cp.async addressing: thread -> (row = t>>3, chunk = t&7), 4 row-groups of 32 ----
    const int crow = t >> 3;               // 0..31
    const int cchk = t & 7;                // 16B chunk (k-offset cchk*8 elems)
    const __nv_bfloat16* gA = g_A  + (size_t)(m0 + crow) * KDIM + kbase + cchk * 8;
    const __nv_bfloat16* gB = g_Bt + (size_t)(n0 + crow) * KDIM + kbase + cchk * 8;

    auto stage_base = [&](int s) { return base + (uint32_t)(s % PIPE) * 32768u; };

    auto issue_stage = [&](int s) {
        uint32_t sb = stage_base(s);
        const __nv_bfloat16* pa = gA + s * TK;
        const __nv_bfloat16* pb = gB + s * TK;
#pragma unroll
        for (int q = 0; q < 4; q++) {
            uint32_t so = swz((uint32_t)(crow + q * 32) * 128u + (uint32_t)cchk * 16u);
            cp_async16(sb + so,          pa + (size_t)(q * 32) * KDIM);
            cp_async16(sb + 16384u + so, pb + (size_t)(q * 32) * KDIM);
        }
    };

    // ---- prologue: PIPE-1 stages in flight ----
#pragma unroll
    for (int s = 0; s < PIPE - 1; s++) { issue_stage(s); CP_COMMIT(); }

    // ---- per-lane ldmatrix offsets (within stage tile) ----
    // A-frag (m16k16): lanes 0-15 -> rows, lanes 16-31 -> rows with k+8
    const uint32_t a_row = (uint32_t)(wm * 32 + (lane & 15));
    const uint32_t a_kb  = (uint32_t)((lane >> 4) * 16);
    // B-frag (n16k16 covering two n8 tiles)
    const uint32_t b_row = (uint32_t)(wn * 64 + (lane & 7) + ((lane >> 4) & 1) * 8);
    const uint32_t b_kb  = (uint32_t)(((lane >> 3) & 1) * 16);

    float acc[2][8][4];
#pragma unroll
    for (int mi = 0; mi < 2; mi++)
#pragma unroll
        for (int ni = 0; ni < 8; ni++)
#pragma unroll
            for (int r = 0; r < 4; r++) acc[mi][ni][r] = 0.f;

    for (int s = 0; s < STAGES; ++s) {
        if (s + PIPE - 1 < STAGES) issue_stage(s + PIPE - 1);
        CP_COMMIT();
        CP_WAIT(PIPE - 2);
        __syncthreads();

        uint32_t sa = stage_base(s);
        uint32_t sbB = sa + 16384u;
#pragma unroll
        for (int kk = 0; kk < 4; kk++) {
            uint32_t a[2][4];
#pragma unroll
            for (int mi = 0; mi < 2; mi++)
                ldsm_x4(a[mi][0], a[mi][1], a[mi][2], a[mi][3],
                        sa + swz((a_row + mi * 16) * 128u + a_kb + kk * 32u));
            uint32_t b[4][4];   // b[g]: regs {b0(t0),b1(t0),b0(t1),b1(t1)} for n-tiles 2g,2g+1
#pragma unroll
            for (int g = 0; g < 4; g++)
                ldsm_x4(b[g][0], b[g][1], b[g][2], b[g][3],
                        sbB + swz((b_row + g * 16) * 128u + b_kb + kk * 32u));
#pragma unroll
            for (int mi = 0; mi < 2; mi++)
#pragma unroll
                for (int g = 0; g < 4; g++) {
                    mma16816(acc[mi][2 * g + 0], a[mi], b[g][0], b[g][1]);
                    mma16816(acc[mi][2 * g + 1], a[mi], b[g][2], b[g][3]);
                }
        }
        __syncthreads();
    }

    // ---- epilogue: write fp32 partial tile ----
    const int er = lane >> 2;          // 0..7
    const int ec = (lane & 3) * 2;     // 0,2,4,6
    float* pz = g_part + (size_t)blockIdx.z * BATCH * UNITS;
#pragma unroll
    for (int mi = 0; mi < 2; mi++) {
#pragma unroll
        for (int ni = 0; ni < 8; ni++) {
            int row = m0 + wm * 32 + mi * 16 + er;
            int col = n0 + wn * 64 + ni * 8 + ec;
            float* p0 = pz + (size_t)row * UNITS + col;
            p0[0] = acc[mi][ni][0];
            p0[1] = acc[mi][ni][1];
            float* p1 = p0 + 8 * UNITS;
            p1[0] = acc[mi][ni][2];
            p1[1] = acc[mi][ni][3];
        }
    }
}

// ---------------- kernel 4: out = sum of 4 split-K partials + bias ----------------
__global__ void reduce_out(const float* __restrict__ bias, float* __restrict__ out) {
    int idx = (blockIdx.x * blockDim.x + threadIdx.x) * 4;
    if (idx >= BATCH * UNITS) return;
    const size_t S = (size_t)BATCH * UNITS;
    float4 a = *(const float4*)(g_part + idx);
    float4 b = *(const float4*)(g_part + idx + S);
    float4 c = *(const float4*)(g_part + idx + 2 * S);
    float4 d = *(const float4*)(g_part + idx + 3 * S);
    float4 bi = *(const float4*)(bias + (idx & (UNITS - 1)));
    float4 r;
    r.x = a.x + b.x + c.x + d.x + bi.x;
    r.y = a.y + b.y + c.y + d.y + bi.y;
    r.z = a.z + b.z + c.z + d.z + bi.z;
    r.w = a.w + b.w + c.w + d.w + bi.w;
    *(float4*)(out + idx) = r;
}

// ---------------- launch ----------------
extern "C" void kernel_launch(void* const* d_in, const int* in_sizes, int n_in,
                              void* d_out, int out_size) {
    const float* x    = (const float*)d_in[0];  // (1024, 512)
    const float* wk   = (const float*)d_in[1];  // (512, 8, 512)
    const float* sc   = (const float*)d_in[2];  // (512, 512)
    const float* bias = (const float*)d_in[3];  // (512,)
    float* out = (float*)d_out;                 // (1024, 512)

    build_A<<<(BATCH * INSZ) / 256, 256>>>(x);
    build_Bt<<<(UNITS * INSZ) / 256, 256>>>(wk, sc);

    const int dsmem = PIPE * 32768;  // 96 KB: 3 stages of [A 16KB | B 16KB]
    cudaFuncSetAttribute(kan_gemm, cudaFuncAttributeMaxDynamicSharedMemorySize, dsmem);
    kan_gemm<<<dim3(UNITS / 128, BATCH / 128, KSPLIT), 256, dsmem>>>();

    reduce_out<<<(BATCH * UNITS / 4) / 256, 256>>>(bias, out);
}

// round 5
// speedup vs baseline: 1.0061x; 1.0061x over previous
#include <cuda_runtime.h>
#include <cuda_bf16.h>
#include <cstdint>

// ---------------- problem constants ----------------
#define BATCH  1024
#define INSZ   512
#define UNITS  512
#define K12    12
#define KDIM   (INSZ * K12)      // 6144
#define KSPLIT 4
#define KPER   (KDIM / KSPLIT)   // 1536
#define TK     64                // K columns per stage (128 B/row bf16)
#define STAGES (KPER / TK)       // 24
#define PIPE   4                 // cp.async pipeline depth

// ---------------- scratch (static device globals; no allocation) ----------------
__device__ __align__(16) __nv_bfloat16 g_A[(size_t)BATCH * KDIM];     // 12.6 MB
__device__ __align__(16) __nv_bfloat16 g_Bt[(size_t)UNITS * KDIM];    // 6.3 MB

// ---------------- helpers ----------------
__device__ __forceinline__ uint32_t smem_u32(const void* p) {
    uint32_t a;
    asm("{ .reg .u64 t; cvta.to.shared.u64 t, %1; cvt.u32.u64 %0, t; }" : "=r"(a) : "l"(p));
    return a;
}
__device__ __forceinline__ uint32_t swz(uint32_t off) { return off ^ ((off >> 3) & 0x70); }

__device__ __forceinline__ void cp_async16(uint32_t saddr, const void* g) {
    asm volatile("cp.async.cg.shared.global [%0], [%1], 16;" :: "r"(saddr), "l"(g) : "memory");
}
#define CP_COMMIT() asm volatile("cp.async.commit_group;" ::: "memory")
#define CP_WAIT(N)  asm volatile("cp.async.wait_group %0;" :: "n"(N) : "memory")

__device__ __forceinline__ void ldsm_x4(uint32_t& r0, uint32_t& r1, uint32_t& r2, uint32_t& r3,
                                        uint32_t addr) {
    asm volatile("ldmatrix.sync.aligned.m8n8.x4.shared.b16 {%0,%1,%2,%3}, [%4];"
                 : "=r"(r0), "=r"(r1), "=r"(r2), "=r"(r3) : "r"(addr));
}
__device__ __forceinline__ void mma16816(float* c, const uint32_t* a, uint32_t b0, uint32_t b1) {
    asm volatile("mma.sync.aligned.m16n8k16.row.col.f32.bf16.bf16.f32 "
                 "{%0,%1,%2,%3}, {%4,%5,%6,%7}, {%8,%9}, {%0,%1,%2,%3};"
                 : "+f"(c[0]), "+f"(c[1]), "+f"(c[2]), "+f"(c[3])
                 : "r"(a[0]), "r"(a[1]), "r"(a[2]), "r"(a[3]), "r"(b0), "r"(b1));
}
__device__ __forceinline__ void red_add_f32(float* p, float v) {
    asm volatile("red.global.add.f32 [%0], %1;" :: "l"(p), "f"(v) : "memory");
}
__device__ __forceinline__ unsigned pkb(__nv_bfloat16 a, __nv_bfloat16 b) {
    return (unsigned)__bfloat16_as_ushort(a) | ((unsigned)__bfloat16_as_ushort(b) << 16);
}

// ---------------- kernel 1: A[b, i*12 + c] = {8 cubic B-spline bases, shi, shi, slo, 0} ----------------
__global__ void build_A(const float* __restrict__ X) {
    int lin = blockIdx.x * blockDim.x + threadIdx.x;
    if (lin >= BATCH * INSZ) return;
    float x = X[lin];

    // uniform knots t_j = -2.2 + 0.4*j, j = 0..11  (GRID=5, ORDER=3, range [-1,1])
    float bb[11];
#pragma unroll
    for (int j = 0; j < 11; j++) {
        float tj = -2.2f + 0.4f * j;
        bb[j] = (x >= tj && x < tj + 0.4f) ? 1.f : 0.f;
    }
#pragma unroll
    for (int k = 1; k <= 3; k++) {
        float inv = 1.f / (0.4f * k);
#pragma unroll
        for (int j = 0; j < 11 - k; j++) {
            float tj = -2.2f + 0.4f * j;
            float tjk1 = -2.2f + 0.4f * (j + k + 1);
            bb[j] = (x - tj) * inv * bb[j] + (tjk1 - x) * inv * bb[j + 1];
        }
    }
    float s = x / (1.f + expf(-x));  // silu
    __nv_bfloat16 shi = __float2bfloat16(s);
    __nv_bfloat16 slo = __float2bfloat16(s - __bfloat162float(shi));

    __nv_bfloat16 h[8];
#pragma unroll
    for (int j = 0; j < 8; j++) h[j] = __float2bfloat16(bb[j]);

    uint2* dst = (uint2*)(g_A + (size_t)lin * K12);
    dst[0] = make_uint2(pkb(h[0], h[1]), pkb(h[2], h[3]));
    dst[1] = make_uint2(pkb(h[4], h[5]), pkb(h[6], h[7]));
    dst[2] = make_uint2(pkb(shi, shi), pkb(slo, __float2bfloat16(0.f)));
}

// ---------------- kernel 2: Bt[o, i*12 + c] = {scale*W_k (k=0..7), schi, sclo, schi, 0} ----------------
__global__ void build_Bt(const float* __restrict__ Wk, const float* __restrict__ scale) {
    int lin = blockIdx.x * blockDim.x + threadIdx.x;
    if (lin >= UNITS * INSZ) return;
    int o = lin & (UNITS - 1);
    int i = lin >> 9;
    float sc = scale[(size_t)i * UNITS + o];

    __nv_bfloat16 c[8];
#pragma unroll
    for (int k = 0; k < 8; k++)
        c[k] = __float2bfloat16(sc * Wk[((size_t)i * 8 + k) * UNITS + o]);
    __nv_bfloat16 schi = __float2bfloat16(sc);
    __nv_bfloat16 sclo = __float2bfloat16(sc - __bfloat162float(schi));

    uint2* dst = (uint2*)(g_Bt + (size_t)o * KDIM + i * K12);
    dst[0] = make_uint2(pkb(c[0], c[1]), pkb(c[2], c[3]));
    dst[1] = make_uint2(pkb(c[4], c[5]), pkb(c[6], c[7]));
    dst[2] = make_uint2(pkb(schi, sclo), pkb(schi, __float2bfloat16(0.f)));
}

// ---------------- kernel 3: out[b,o] = bias[o] (atomic accumulation base) ----------------
__global__ void init_out(const float* __restrict__ bias, float* __restrict__ out) {
    int idx = (blockIdx.x * blockDim.x + threadIdx.x) * 4;
    if (idx >= BATCH * UNITS) return;
    *(float4*)(out + idx) = *(const float4*)(bias + (idx & (UNITS - 1)));
}

// ---------------- kernel 4: split-K bf16 mma.sync GEMM, epilogue red.global.add ----------------
// CTA tile 128x128, K-stage 64, 4-stage cp.async pipeline.
// RACE-FREE single barrier per stage: order is  WAIT(s) -> barrier -> ISSUE(s+3) -> COMPUTE(s).
// Writes to buffer (s+3)%4 == (s-1)%4 occur after barrier(s); all reads of that buffer
// were in iteration s-1, before barrier(s). cp.async data readiness is via CP_WAIT+barrier.
__global__ __launch_bounds__(256, 1)
void kan_gemm(float* __restrict__ out) {
    extern __shared__ char dyn[];
    const uint32_t base = smem_u32(dyn);   // PIPE stages of [A 16KB | B 16KB]

    const int t   = threadIdx.x;
    const int wid = t >> 5, lane = t & 31;
    const int wm  = wid & 3;               // 4 warp-rows  -> 32 m each
    const int wn  = wid >> 2;              // 2 warp-cols  -> 64 n each
    const int m0  = blockIdx.y * 128;
    const int n0  = blockIdx.x * 128;
    const int kbase = blockIdx.z * KPER;

    // ---- cp.async addressing: thread -> (row = t>>3, chunk = t&7) ----
    const int crow = t >> 3;               // 0..31
    const int cchk = t & 7;                // 16B chunk (k-offset cchk*8 elems)
    const __nv_bfloat16* gA = g_A  + (size_t)(m0 + crow) * KDIM + kbase + cchk * 8;
    const __nv_bfloat16* gB = g_Bt + (size_t)(n0 + crow) * KDIM + kbase + cchk * 8;

    auto stage_base = [&](int s) { return base + (uint32_t)(s % PIPE) * 32768u; };

    auto issue_stage = [&](int s) {
        uint32_t sb = stage_base(s);
        const __nv_bfloat16* pa = gA + s * TK;
        const __nv_bfloat16* pb = gB + s * TK;
#pragma unroll
        for (int q = 0; q < 4; q++) {
            uint32_t so = swz((uint32_t)(crow + q * 32) * 128u + (uint32_t)cchk * 16u);
            cp_async16(sb + so,          pa + (size_t)(q * 32) * KDIM);
            cp_async16(sb + 16384u + so, pb + (size_t)(q * 32) * KDIM);
        }
    };

    // ---- prologue: PIPE-1 stages in flight ----
#pragma unroll
    for (int s = 0; s < PIPE - 1; s++) { issue_stage(s); CP_COMMIT(); }

    // ---- per-lane ldmatrix offsets (within stage tile) ----
    const uint32_t a_row = (uint32_t)(wm * 32 + (lane & 15));
    const uint32_t a_kb  = (uint32_t)((lane >> 4) * 16);
    const uint32_t b_row = (uint32_t)(wn * 64 + (lane & 7) + ((lane >> 4) & 1) * 8);
    const uint32_t b_kb  = (uint32_t)(((lane >> 3) & 1) * 16);

    float acc[2][8][4];
#pragma unroll
    for (int mi = 0; mi < 2; mi++)
#pragma unroll
        for (int ni = 0; ni < 8; ni++)
#pragma unroll
            for (int r = 0; r < 4; r++) acc[mi][ni][r] = 0.f;

    for (int s = 0; s < STAGES; ++s) {
        // wait for stage s data (3 groups in flight beyond it at most)
        CP_WAIT(PIPE - 2);
        __syncthreads();           // all threads' stage-s copies visible; all stage-(s-1) reads done

        // refill: issue stage s+PIPE-1 AFTER the barrier (writes buffer (s-1)%PIPE safely)
        if (s + PIPE - 1 < STAGES) issue_stage(s + PIPE - 1);
        CP_COMMIT();               // commit (possibly empty) group to keep wait-count semantics

        uint32_t sa = stage_base(s);
        uint32_t sbB = sa + 16384u;

        // ---- load the ENTIRE stage's fragments into registers first (hide LDSM latency) ----
        uint32_t a[2][4][4];   // [mi][kk][reg]
        uint32_t b[4][4][4];   // [g][kk][reg]
#pragma unroll
        for (int kk = 0; kk < 4; kk++) {
#pragma unroll
            for (int mi = 0; mi < 2; mi++)
                ldsm_x4(a[mi][kk][0], a[mi][kk][1], a[mi][kk][2], a[mi][kk][3],
                        sa + swz((a_row + mi * 16) * 128u + a_kb + kk * 32u));
#pragma unroll
            for (int g = 0; g < 4; g++)
                ldsm_x4(b[g][kk][0], b[g][kk][1], b[g][kk][2], b[g][kk][3],
                        sbB + swz((b_row + g * 16) * 128u + b_kb + kk * 32u));
        }

        // ---- 64 back-to-back HMMAs ----
#pragma unroll
        for (int kk = 0; kk < 4; kk++)
#pragma unroll
            for (int mi = 0; mi < 2; mi++)
#pragma unroll
                for (int g = 0; g < 4; g++) {
                    mma16816(acc[mi][2 * g + 0], a[mi][kk], b[g][kk][0], b[g][kk][1]);
                    mma16816(acc[mi][2 * g + 1], a[mi][kk], b[g][kk][2], b[g][kk][3]);
                }
    }

    // ---- epilogue: atomic-accumulate fp32 tile into out (pre-initialized with bias) ----
    const int er = lane >> 2;          // 0..7
    const int ec = (lane & 3) * 2;     // 0,2,4,6
#pragma unroll
    for (int mi = 0; mi < 2; mi++) {
#pragma unroll
        for (int ni = 0; ni < 8; ni++) {
            int row = m0 + wm * 32 + mi * 16 + er;
            int col = n0 + wn * 64 + ni * 8 + ec;
            float* p0 = out + (size_t)row * UNITS + col;
            red_add_f32(p0 + 0, acc[mi][ni][0]);
            red_add_f32(p0 + 1, acc[mi][ni][1]);
            float* p1 = p0 + 8 * UNITS;
            red_add_f32(p1 + 0, acc[mi][ni][2]);
            red_add_f32(p1 + 1, acc[mi][ni][3]);
        }
    }
}

// ---------------- launch ----------------
extern "C" void kernel_launch(void* const* d_in, const int* in_sizes, int n_in,
                              void* d_out, int out_size) {
    const float* x    = (const float*)d_in[0];  // (1024, 512)
    const float* wk   = (const float*)d_in[1];  // (512, 8, 512)
    const float* sc   = (const float*)d_in[2];  // (512, 512)
    const float* bias = (const float*)d_in[3];  // (512,)
    float* out = (float*)d_out;                 // (1024, 512)

    build_A<<<(BATCH * INSZ) / 256, 256>>>(x);
    build_Bt<<<(UNITS * INSZ) / 256, 256>>>(wk, sc);
    init_out<<<(BATCH * UNITS / 4) / 256, 256>>>(bias, out);

    const int dsmem = PIPE * 32768;  // 128 KB: 4 stages of [A 16KB | B 16KB]
    cudaFuncSetAttribute(kan_gemm, cudaFuncAttributeMaxDynamicSharedMemorySize, dsmem);
    kan_gemm<<<dim3(UNITS / 128, BATCH / 128, KSPLIT), 256, dsmem>>>(out);
}